// round 4
// baseline (speedup 1.0000x reference)
#include <cuda_runtime.h>
#include <cstdint>

// Output = sigmoid(2.0) everywhere (reference's s = exp(y-y) == 1).
// 64 MiB constant fill. STG path plateaued at ~12.1us across two launch
// shapes (L2=49%, L1=59%, DRAM=9%) -> SM-side store path saturated.
// This round: route stores through the async proxy (cp.async.bulk
// SMEM->GMEM), bypassing STG/L1tex-store wavefronts. One 32KB SMEM buffer
// per block, replicated to 4 distinct 32KB GMEM windows.

static constexpr int THREADS      = 256;
static constexpr int SMEM_BYTES   = 32 * 1024;              // 32 KB source tile
static constexpr int BULKS_PER_CTA = 4;                      // 4 x 32KB = 128 KB/CTA
static constexpr int BYTES_PER_CTA = SMEM_BYTES * BULKS_PER_CTA;

__device__ __forceinline__ uint32_t smem_u32(const void* p) {
    uint32_t a;
    asm("{ .reg .u64 t; cvta.to.shared.u64 t, %1; cvt.u32.u64 %0, t; }"
        : "=r"(a) : "l"(p));
    return a;
}

__global__ void __launch_bounds__(THREADS) fill_sigmoid2_tma(float* __restrict__ out) {
    __shared__ __align__(128) float4 buf[SMEM_BYTES / 16];   // 2048 float4

    const float v = 0.8807970779778823f;                     // sigmoid(2.0)
    const float4 val = make_float4(v, v, v, v);
    const int tid = threadIdx.x;

    // Fill the 32KB SMEM tile: 8 STS.128 per thread.
#pragma unroll
    for (int k = 0; k < 8; k++) {
        buf[tid + k * THREADS] = val;
    }
    __syncthreads();
    // Make generic-proxy SMEM writes visible to the async proxy.
    asm volatile("fence.proxy.async.shared::cta;" ::: "memory");

    if (tid == 0) {
        uint32_t src = smem_u32(buf);
        char* dst = (char*)out + (size_t)blockIdx.x * BYTES_PER_CTA;
#pragma unroll
        for (int j = 0; j < BULKS_PER_CTA; j++) {
            asm volatile(
                "cp.async.bulk.global.shared::cta.bulk_group [%0], [%1], %2;"
                :: "l"(dst + (size_t)j * SMEM_BYTES), "r"(src), "n"(SMEM_BYTES)
                : "memory");
        }
        asm volatile("cp.async.bulk.commit_group;" ::: "memory");
        asm volatile("cp.async.bulk.wait_group 0;" ::: "memory");
    }
}

// Fallback for any bytes not covered by the bulk grid (0 for this shape).
__global__ void fill_sigmoid2_tail(float* __restrict__ out, long long start, long long n) {
    long long i = start + (long long)blockIdx.x * blockDim.x + threadIdx.x;
    if (i < n) out[i] = 0.8807970779778823f;
}

extern "C" void kernel_launch(void* const* d_in, const int* in_sizes, int n_in,
                              void* d_out, int out_size) {
    (void)d_in; (void)in_sizes; (void)n_in;
    float* out = (float*)d_out;

    long long total_bytes = (long long)out_size * 4;         // 67,108,864
    int blocks = (int)(total_bytes / BYTES_PER_CTA);         // 512 exact
    long long covered_elems = (long long)blocks * (BYTES_PER_CTA / 4);

    if (blocks > 0) {
        fill_sigmoid2_tma<<<blocks, THREADS>>>(out);
    }
    long long rem = (long long)out_size - covered_elems;     // 0 here
    if (rem > 0) {
        int t = 256;
        int b = (int)((rem + t - 1) / t);
        fill_sigmoid2_tail<<<b, t>>>(out, covered_elems, (long long)out_size);
    }
}

// round 6
// speedup vs baseline: 1.0130x; 1.0130x over previous
#include <cuda_runtime.h>
#include <cstdint>

// Output = sigmoid(2.0) everywhere (reference's s = exp(y-y) == 1).
// 64 MiB constant fill. STG-only and TMA-only both plateau at ~5.5 TB/s
// (12.1us / 13.9us) with identical L2~49% fingerprints -> suspected shared
// LTS write-port cap. This round superposes BOTH store engines per block:
// 64 KB via cp.async.bulk (SMEM->GMEM) + 64 KB via STG.128, concurrently.
// Bimodal prediction: ~7us if per-path limits, ~12us if shared LTS wall.
// (Resubmission of R4 kernel — R5 bench was an infra failure, no signal.)

static constexpr int THREADS       = 256;
static constexpr int SMEM_BYTES    = 32 * 1024;               // 32 KB tile
static constexpr int TMA_BYTES     = 2 * SMEM_BYTES;          // 64 KB via bulk
static constexpr int STG_BYTES     = 64 * 1024;               // 64 KB via STG
static constexpr int BYTES_PER_CTA = TMA_BYTES + STG_BYTES;   // 128 KB

__device__ __forceinline__ uint32_t smem_u32(const void* p) {
    uint32_t a;
    asm("{ .reg .u64 t; cvta.to.shared.u64 t, %1; cvt.u32.u64 %0, t; }"
        : "=r"(a) : "l"(p));
    return a;
}

__global__ void __launch_bounds__(THREADS) fill_sigmoid2_hybrid(float* __restrict__ out) {
    __shared__ __align__(128) float4 buf[SMEM_BYTES / 16];    // 2048 float4

    const float v = 0.8807970779778823f;                      // sigmoid(2.0)
    const float4 val = make_float4(v, v, v, v);
    const int tid = threadIdx.x;

    // Fill 32 KB SMEM tile: 8 STS.128 per thread.
#pragma unroll
    for (int k = 0; k < 8; k++) {
        buf[tid + k * THREADS] = val;
    }
    __syncthreads();
    asm volatile("fence.proxy.async.shared::cta;" ::: "memory");

    char* window = (char*)out + (size_t)blockIdx.x * BYTES_PER_CTA;

    // Kick off the async bulk stores first so the engines drain while the
    // warps grind through the STG half.
    if (tid == 0) {
        uint32_t src = smem_u32(buf);
        asm volatile(
            "cp.async.bulk.global.shared::cta.bulk_group [%0], [%1], %2;"
            :: "l"(window), "r"(src), "n"(SMEM_BYTES) : "memory");
        asm volatile(
            "cp.async.bulk.global.shared::cta.bulk_group [%0], [%1], %2;"
            :: "l"(window + SMEM_BYTES), "r"(src), "n"(SMEM_BYTES) : "memory");
        asm volatile("cp.async.bulk.commit_group;" ::: "memory");
    }

    // STG half: 64 KB = 4096 float4, 16 per thread, warp-coalesced stride.
    float4* stg_base = (float4*)(window + TMA_BYTES);
#pragma unroll
    for (int k = 0; k < 16; k++) {
        stg_base[tid + k * THREADS] = val;
    }

    // Drain bulk stores before CTA exit.
    if (tid == 0) {
        asm volatile("cp.async.bulk.wait_group 0;" ::: "memory");
    }
}

// Fallback for any uncovered remainder (0 for this shape).
__global__ void fill_sigmoid2_tail(float* __restrict__ out, long long start, long long n) {
    long long i = start + (long long)blockIdx.x * blockDim.x + threadIdx.x;
    if (i < n) out[i] = 0.8807970779778823f;
}

extern "C" void kernel_launch(void* const* d_in, const int* in_sizes, int n_in,
                              void* d_out, int out_size) {
    (void)d_in; (void)in_sizes; (void)n_in;
    float* out = (float*)d_out;

    long long total_bytes = (long long)out_size * 4;          // 67,108,864
    int blocks = (int)(total_bytes / BYTES_PER_CTA);          // 512 exact
    long long covered_elems = (long long)blocks * (BYTES_PER_CTA / 4);

    if (blocks > 0) {
        fill_sigmoid2_hybrid<<<blocks, THREADS>>>(out);
    }
    long long rem = (long long)out_size - covered_elems;      // 0 here
    if (rem > 0) {
        int t = 256;
        int b = (int)((rem + t - 1) / t);
        fill_sigmoid2_tail<<<b, t>>>(out, covered_elems, (long long)out_size);
    }
}

// round 7
// speedup vs baseline: 1.1858x; 1.1705x over previous
#include <cuda_runtime.h>

// FINAL: Output is the constant sigmoid(2.0) everywhere (s = exp(y-y) == 1).
// 64 MiB fp32 constant fill. Measured across four store strategies
// (STG x1, STG x8, cp.async.bulk, hybrid), all plateau at ~5.5 TB/s ->
// path-independent LTS write-port cap. 67.1 MB / 5.5 TB/s = 12.2 us = this
// kernel's measured 12.1 us. At the fill roofline; this is the best shape.

#ifndef VEC_PER_THREAD
#define VEC_PER_THREAD 8   // 8 x float4 = 128 B per thread
#endif

__global__ void __launch_bounds__(256) fill_sigmoid2_v8(float4* __restrict__ out4) {
    const float v = 0.8807970779778823f; // sigmoid(2.0)
    const float4 val = make_float4(v, v, v, v);
    // Block covers 256*8 = 2048 consecutive float4s (32 KB), strided so each
    // STG.128 is a contiguous 4KB warp transaction. Max index = 4,194,304
    // float4s -> fits in 32-bit; ptxas keeps address math to 1 IMAD/store.
    unsigned base = blockIdx.x * (256u * VEC_PER_THREAD) + threadIdx.x;
#pragma unroll
    for (int k = 0; k < VEC_PER_THREAD; k++) {
        out4[base + (unsigned)k * 256u] = val;
    }
}

__global__ void fill_sigmoid2_tail(float* __restrict__ out, int start, int n) {
    int i = start + blockIdx.x * blockDim.x + threadIdx.x;
    if (i < n) out[i] = 0.8807970779778823f;
}

extern "C" void kernel_launch(void* const* d_in, const int* in_sizes, int n_in,
                              void* d_out, int out_size) {
    (void)d_in; (void)in_sizes; (void)n_in;
    float* out = (float*)d_out;

    const int threads = 256;
    const int f4_per_block = threads * VEC_PER_THREAD;        // 2048 float4 = 32 KB
    int n4 = out_size / 4;                                    // 4,194,304
    int blocks = n4 / f4_per_block;                           // 2048 exact
    int covered4 = blocks * f4_per_block;

    if (blocks > 0) {
        fill_sigmoid2_v8<<<blocks, threads>>>((float4*)out);
    }
    // Remainder (0 for this shape, kept for generality)
    int rem_elems = out_size - covered4 * 4;
    if (rem_elems > 0) {
        int t = 256;
        int b = (rem_elems + t - 1) / t;
        fill_sigmoid2_tail<<<b, t>>>(out, covered4 * 4, out_size);
    }
}